// round 9
// baseline (speedup 1.0000x reference)
#include <cuda_runtime.h>
#include <cuda_bf16.h>

// YOLO layer: x [B=16, C=255, 64, 64] fp32, anchors [3,2] fp32.
// pred = x.reshape(B, 3, 85, 64, 64).transpose(0,1,3,4,2)
// Outputs concatenated in d_out (float32):
//   boxes [B,3,64,64,4]  : 786,432    elems at offset 0
//   conf  [B,3,64,64]    : 196,608    elems at offset 786,432
//   cls   [B,3,64,64,80] : 15,728,640 elems at offset 983,040
//
// R8: smem-free direct rewrite. R7 showed DRAM/L2/L1 all ~50% with
// issue 21% and flat time -> the two-phase (LDG->bar->LDS) block
// structure was latency-binding, not any pipe. Reads are coalesced in
// the INPUT layout for any thread mapping; only stores need layout
// care. New mapping:
//   cls: thread=(p, j0): loads = 2 channels x 16 consecutive p per warp
//        (2x64B segments/LDG.32); stores = even/odd lanes form 32B
//        contiguous pairs per position (sector-perfect STG.128).
//        40 LDG + 10 STG.128 per thread, no smem, no __syncthreads.
//   boxes/conf: thread=position, 5 coalesced LDG.32, contiguous
//        STG.128 + STG.32.
// sigmoid via MUFU.TANH: sig(x) = fma(0.5, tanh(0.5x), 0.5).

#define NT 256

__device__ __forceinline__ float sigf(float v) {
    float t;
    asm("tanh.approx.f32 %0, %1;" : "=f"(t) : "f"(v * 0.5f));
    return fmaf(0.5f, t, 0.5f);
}

__global__ __launch_bounds__(NT) void yolo_kernel(
    const float* __restrict__ x,
    const float* __restrict__ anchors,
    float* __restrict__ out)
{
    constexpr int A    = 3;
    constexpr int CH   = 85;
    constexpr int P    = 64 * 64;                     // 4096 positions per (b,a)
    constexpr int Btot = 16;
    constexpr int CONF_OFF = Btot * A * P * 4;        // 786432
    constexpr int CLS_OFF  = CONF_OFF + Btot * A * P; // 983040
    constexpr int CLS_BLKS = Btot * A * (P / 128);    // 1536 (128 positions/block)

    const int blk = blockIdx.x;
    const int t   = threadIdx.x;

    if (blk < CLS_BLKS) {
        // ---- cls: 128 positions x 80 channels per block ----
        const int ba = blk >> 5;                      // 32 tiles per (b,a)
        const int pg = ((blk & 31) << 7) + (t >> 1);  // global position
        const int j0 = t & 1;                         // chunk parity
        const float* xin = x + (size_t)ba * CH * P + pg;
        float4* ocls = reinterpret_cast<float4*>(
            out + CLS_OFF + (size_t)(ba * P + pg) * 80);
        #pragma unroll
        for (int k = 0; k < 10; k++) {
            const int j = 2 * k + j0;                 // float4 chunk 0..19
            const int c = 5 + 4 * j;                  // channels c..c+3
            float4 v;
            v.x = sigf(xin[(c + 0) * P]);
            v.y = sigf(xin[(c + 1) * P]);
            v.z = sigf(xin[(c + 2) * P]);
            v.w = sigf(xin[(c + 3) * P]);
            ocls[j] = v;
        }
    } else {
        // ---- boxes + conf: 256 positions per block, thread = position ----
        const int b2 = blk - CLS_BLKS;
        const int ba = b2 >> 4;                       // 16 tiles per (b,a)
        const int pg = ((b2 & 15) << 8) + t;
        const int a  = ba - (ba / A) * A;
        const float aw = __ldg(anchors + a * 2 + 0);
        const float ah = __ldg(anchors + a * 2 + 1);
        const float* xin = x + (size_t)ba * CH * P + pg;
        float4 b;
        b.x = (sigf(xin[0 * P]) + (float)(pg >> 6)) * (1.0f / 64.0f);
        b.y = (sigf(xin[1 * P]) + (float)(pg & 63)) * (1.0f / 64.0f);
        b.z = __expf(xin[2 * P]) * aw;
        b.w = __expf(xin[3 * P]) * ah;
        reinterpret_cast<float4*>(out)[ba * P + pg] = b;
        out[CONF_OFF + ba * P + pg] = sigf(xin[4 * P]);
    }
}

extern "C" void kernel_launch(void* const* d_in, const int* in_sizes, int n_in,
                              void* d_out, int out_size) {
    const float* x       = (const float*)d_in[0];
    const float* anchors = (const float*)d_in[1];
    float*       out     = (float*)d_out;
    // 1536 cls blocks + 768 boxes/conf blocks
    yolo_kernel<<<2304, NT>>>(x, anchors, out);
}

// round 10
// speedup vs baseline: 1.0399x; 1.0399x over previous
#include <cuda_runtime.h>
#include <cuda_bf16.h>

// YOLO layer: x [B=16, C=255, 64, 64] fp32, anchors [3,2] fp32.
// pred = x.reshape(B, 3, 85, 64, 64).transpose(0,1,3,4,2)
// Outputs concatenated in d_out (float32):
//   boxes [B,3,64,64,4]  : 786,432    elems at offset 0
//   conf  [B,3,64,64]    : 196,608    elems at offset 786,432
//   cls   [B,3,64,64,80] : 15,728,640 elems at offset 983,040
//
// R9: MLP boost. R6-R8 all land ~21us with every pipe at ~50% and
// issue 15% -> outstanding-load limited. regs=32 capped ptxas at ~8
// in-flight loads/warp. This version front-batches 20 independent
// LDG.32 into registers per phase (2 phases), then computes, then 5
// STG.128. __launch_bounds__(256,4) gives ~60 regs: 32 warps/SM x 20
// in-flight = ~640 outstanding vs ~448 before.
// Memory mapping unchanged from R8 (sector-perfect both sides):
//   cls: thread=(p, j0); warp loads = 2 channels x 16 consecutive p
//        (2x64B segments per LDG.32); stores = even/odd lane pairs form
//        32B-contiguous chunks.
//   boxes/conf: thread=position, coalesced LDG.32, STG.128 + STG.32.
// sigmoid via MUFU.TANH: sig(x) = fma(0.5, tanh(0.5x), 0.5).

#define NT 256

__device__ __forceinline__ float sigf(float v) {
    float t;
    asm("tanh.approx.f32 %0, %1;" : "=f"(t) : "f"(v * 0.5f));
    return fmaf(0.5f, t, 0.5f);
}

__global__ __launch_bounds__(NT, 4) void yolo_kernel(
    const float* __restrict__ x,
    const float* __restrict__ anchors,
    float* __restrict__ out)
{
    constexpr int A    = 3;
    constexpr int CH   = 85;
    constexpr int P    = 64 * 64;                     // 4096 positions per (b,a)
    constexpr int Btot = 16;
    constexpr int CONF_OFF = Btot * A * P * 4;        // 786432
    constexpr int CLS_OFF  = CONF_OFF + Btot * A * P; // 983040
    constexpr int CLS_BLKS = Btot * A * (P / 128);    // 1536 (128 positions/block)

    const int blk = blockIdx.x;
    const int t   = threadIdx.x;

    if (blk < CLS_BLKS) {
        // ---- cls: 128 positions x 80 channels per block ----
        const int ba = blk >> 5;                      // 32 tiles per (b,a)
        const int pg = ((blk & 31) << 7) + (t >> 1);  // global position
        const int j0 = t & 1;                         // chunk parity
        const float* xin = x + (size_t)ba * CH * P + pg + (size_t)(5 + 4 * j0) * P;
        float4* ocls = reinterpret_cast<float4*>(
            out + CLS_OFF + (size_t)(ba * P + pg) * 80);

        // Two phases; each: 20 front-batched independent LDG.32 ->
        // 20 MUFU.TANH -> 5 STG.128.
        #pragma unroll
        for (int h = 0; h < 2; h++) {
            float v[20];
            // chunk j = 2*(5h+k) + j0, channels 4j+5 .. 4j+8; xin already
            // offset by (5 + 4*j0)*P, so element (k,e) is at (8*(5h+k)+e)*P.
            #pragma unroll
            for (int k = 0; k < 5; k++) {
                #pragma unroll
                for (int e = 0; e < 4; e++) {
                    v[k * 4 + e] = xin[(size_t)(8 * (5 * h + k) + e) * P];
                }
            }
            #pragma unroll
            for (int i = 0; i < 20; i++) v[i] = sigf(v[i]);
            #pragma unroll
            for (int k = 0; k < 5; k++) {
                float4 o;
                o.x = v[k * 4 + 0];
                o.y = v[k * 4 + 1];
                o.z = v[k * 4 + 2];
                o.w = v[k * 4 + 3];
                ocls[2 * (5 * h + k) + j0] = o;
            }
        }
    } else {
        // ---- boxes + conf: 256 positions per block, thread = position ----
        const int b2 = blk - CLS_BLKS;
        const int ba = b2 >> 4;                       // 16 tiles per (b,a)
        const int pg = ((b2 & 15) << 8) + t;
        const int a  = ba - (ba / A) * A;
        const float aw = __ldg(anchors + a * 2 + 0);
        const float ah = __ldg(anchors + a * 2 + 1);
        const float* xin = x + (size_t)ba * CH * P + pg;
        const float x0 = xin[0 * P];
        const float x1 = xin[1 * P];
        const float x2 = xin[2 * P];
        const float x3 = xin[3 * P];
        const float x4 = xin[4 * P];
        float4 b;
        b.x = (sigf(x0) + (float)(pg >> 6)) * (1.0f / 64.0f);
        b.y = (sigf(x1) + (float)(pg & 63)) * (1.0f / 64.0f);
        b.z = __expf(x2) * aw;
        b.w = __expf(x3) * ah;
        reinterpret_cast<float4*>(out)[ba * P + pg] = b;
        out[CONF_OFF + ba * P + pg] = sigf(x4);
    }
}

extern "C" void kernel_launch(void* const* d_in, const int* in_sizes, int n_in,
                              void* d_out, int out_size) {
    const float* x       = (const float*)d_in[0];
    const float* anchors = (const float*)d_in[1];
    float*       out     = (float*)d_out;
    // 1536 cls blocks + 768 boxes/conf blocks
    yolo_kernel<<<2304, NT>>>(x, anchors, out);
}

// round 11
// speedup vs baseline: 1.0664x; 1.0255x over previous
#include <cuda_runtime.h>
#include <cuda_bf16.h>

// YOLO layer: x [B=16, C=255, 64, 64] fp32, anchors [3,2] fp32.
// pred = x.reshape(B, 3, 85, 64, 64).transpose(0,1,3,4,2)
// Outputs concatenated in d_out (float32):
//   boxes [B,3,64,64,4]  : 786,432    elems at offset 0
//   conf  [B,3,64,64]    : 196,608    elems at offset 786,432
//   cls   [B,3,64,64,80] : 15,728,640 elems at offset 983,040
//
// R10: L1tex-wavefront diet. All prior kernels (~21us, all pipes ~50%)
// stored cls as warps of STG.128 at 320B position stride -> 16 distinct
// 128B lines = 16 L1tex wavefronts per warp-store (~2M store wavefronts,
// ~10us of LSU line processing chip-wide). This version stages through
// smem and stores the per-tile cls region (64 pos x 80 ch = 20KB,
// CONTIGUOUS in output) in output-linear order: warp STG.128 = 512B
// contiguous = 4 wavefronts (4x fewer). Loads stay input-coalesced
// (warp-LDG.128 = 4 lines). Streaming .cs hints on gmem traffic.
// sigmoid via MUFU.TANH: sig(x) = fma(0.5, tanh(0.5x), 0.5).

#define NT 256
#define TP 64
#define PITCH 65            // floats per smem channel row; bank = (c + p) % 32

__device__ __forceinline__ float sigf(float v) {
    float t;
    asm("tanh.approx.f32 %0, %1;" : "=f"(t) : "f"(v * 0.5f));
    return fmaf(0.5f, t, 0.5f);
}

__global__ __launch_bounds__(NT) void yolo_kernel(
    const float* __restrict__ x,
    const float* __restrict__ anchors,
    float* __restrict__ out)
{
    constexpr int A    = 3;
    constexpr int CH   = 85;
    constexpr int P    = 64 * 64;                     // 4096 positions per (b,a)
    constexpr int Btot = 16;
    constexpr int CONF_OFF = Btot * A * P * 4;        // 786432
    constexpr int CLS_OFF  = CONF_OFF + Btot * A * P; // 983040

    __shared__ float tile[CH * PITCH];                // 85 x 65 = 22.1 KB

    const int blk = blockIdx.x;
    const int ba  = blk >> 6;                         // 64 tiles per (b,a)
    const int p0  = (blk & 63) * TP;
    const int t   = threadIdx.x;

    // ---- Load: 85 ch x 16 float4, input-coalesced (4 wavefronts/warp) ----
    const float4* xin4 = reinterpret_cast<const float4*>(
        x + (size_t)ba * CH * P + p0);                // p0 multiple of 64 -> aligned
    #pragma unroll
    for (int k = 0; k < 6; k++) {
        const int idx = t + k * NT;                   // 0..1535, need < 1360
        if (idx < CH * (TP / 4)) {
            const int c = idx >> 4;                   // float4 row index
            const int q = idx & 15;
            float4 v = __ldcs(xin4 + c * (P / 4) + q);
            const int base = c * PITCH + 4 * q;
            tile[base + 0] = v.x;                     // 4x STS.32, ~2-way conflicts
            tile[base + 1] = v.y;
            tile[base + 2] = v.z;
            tile[base + 3] = v.w;
        }
    }
    __syncthreads();

    // ---- cls: output-linear stores. Tile's cls region = 1280 float4
    //      contiguous; thread t writes f = t + 256k. Warp STG.128 spans
    //      512B contiguous -> 4 L1tex wavefronts. ----
    {
        float4* ocls4 = reinterpret_cast<float4*>(
            out + CLS_OFF + (size_t)(ba * P + p0) * 80);
        #pragma unroll
        for (int k = 0; k < 5; k++) {
            const int f = t + k * NT;                 // 0..1279
            const int p = f / 20;                     // position in tile (0..63)
            const int j = f - 20 * p;                 // float4 chunk (0..19)
            const int c = 5 + 4 * j;                  // channels c..c+3
            float4 o;
            o.x = sigf(tile[(c + 0) * PITCH + p]);
            o.y = sigf(tile[(c + 1) * PITCH + p]);
            o.z = sigf(tile[(c + 2) * PITCH + p]);
            o.w = sigf(tile[(c + 3) * PITCH + p]);
            __stcs(ocls4 + f, o);
        }
    }

    // ---- boxes: threads 0..63, STG.128; warp = 512B contiguous ----
    if (t < TP) {
        const int a  = ba - (ba / A) * A;
        const float aw = __ldg(anchors + a * 2 + 0);
        const float ah = __ldg(anchors + a * 2 + 1);
        const int pg = p0 + t;
        float4 b;
        b.x = (sigf(tile[0 * PITCH + t]) + (float)(pg >> 6)) * (1.0f / 64.0f);
        b.y = (sigf(tile[1 * PITCH + t]) + (float)(pg & 63)) * (1.0f / 64.0f);
        b.z = __expf(tile[2 * PITCH + t]) * aw;
        b.w = __expf(tile[3 * PITCH + t]) * ah;
        __stcs(reinterpret_cast<float4*>(out) + ba * P + pg, b);
    }
    // ---- conf: threads 64..127, scalar; warp = 128B line-contiguous ----
    else if (t < 2 * TP) {
        const int p = t - TP;                         // 0..63
        __stcs(out + CONF_OFF + ba * P + p0 + p, sigf(tile[4 * PITCH + p]));
    }
}

extern "C" void kernel_launch(void* const* d_in, const int* in_sizes, int n_in,
                              void* d_out, int out_size) {
    const float* x       = (const float*)d_in[0];
    const float* anchors = (const float*)d_in[1];
    float*       out     = (float*)d_out;
    yolo_kernel<<<3072, NT>>>(x, anchors, out);
}